// round 3
// baseline (speedup 1.0000x reference)
#include <cuda_runtime.h>
#include <math.h>

// Problem constants
#define NBATCH 16
#define NC1 8
#define NC2 16
#define NM 63      /* k1 = m-31, m in [0,63) */
#define NK2 32     /* k2 in [0,32) */
#define NF (NM*NK2)  /* 2016 frequency points */
#define NPIX 16384   /* 128*128 */

// ---------------- device scratch ----------------
__device__ float   g_ksym[128*4096];
__device__ float2  g_Kf[128*NF];
__device__ float2  g_Ff[128*NF];
__device__ float2  g_Cf[256*NF];
__device__ float2  g_Q[640*4096];           // Q [ch][k2*128+n1]
__device__ float   g_u[256*NPIX];
__device__ float   g_v[256*NPIX];
__device__ float2  g_Ey[64*32];
__device__ float2  g_Ex[64*64];
__device__ float2  g_WxT[63*128];
__device__ float2  g_WyT[32*128];
__device__ float   g_MU[NF];
__device__ float   g_MV[NF];
__device__ int     g_I[120], g_J[120];

// ---------------- table init (parallel) ----------------
__global__ void k_init() {
    int tid = blockIdx.x*256 + threadIdx.x;
    int stride = gridDim.x*256;
    for (int idx = tid; idx < 64*32; idx += stride) {
        int y = idx >> 5, k2 = idx & 31;
        float s, c; sincospif(-2.0f * (float)(k2*y) / 64.0f, &s, &c);
        g_Ey[idx] = make_float2(c, s);
    }
    for (int idx = tid; idx < 64*64; idx += stride) {
        int m = idx >> 6, x = idx & 63; int k1 = m - 31;
        float s, c; sincospif(-2.0f * (float)(k1*x) / 64.0f, &s, &c);
        g_Ex[idx] = make_float2(c, s);
    }
    for (int idx = tid; idx < 63*128; idx += stride) {
        int m = idx >> 7, n1 = idx & 127; int k1 = m - 31;
        float s, c; sincospif(2.0f * (float)(k1*n1) / 128.0f, &s, &c);
        g_WxT[idx] = make_float2(c, s);
    }
    for (int idx = tid; idx < 32*128; idx += stride) {
        int k2 = idx >> 7, n2 = idx & 127;
        float s, c; sincospif(2.0f * (float)(k2*n2) / 128.0f, &s, &c);
        float sc = ((k2 == 0) ? 1.0f : 2.0f) * (2.0f / 16384.0f);
        g_WyT[idx] = make_float2(c * sc, s * sc);
    }
    for (int idx = tid; idx < NF; idx += stride) {
        int m = idx >> 5, k2 = idx & 31; int k1 = m - 31;
        float den = (float)(k1*k1 + k2*k2);
        if (den == 0.0f) den = 1.0f;
        g_MU[idx] =  (float)k2 / den;
        g_MV[idx] = -(float)k1 / den;
    }
    for (int p = tid; p < 120; p += stride) {
        int off = p, i = 0, cnt = 15;
        while (off >= cnt) { off -= cnt; i++; cnt--; }
        g_I[p] = i; g_J[p] = i + 1 + off;
    }
}

// ---------------- D4 kernel symmetrization (smem) ----------------
__global__ void __launch_bounds__(256) k_sym(const float* __restrict__ kin) {
    __shared__ float s[4096];
    int ch = blockIdx.x, t = threadIdx.x;
    const float* src = kin + ch*4096;
    for (int i = t; i < 4096; i += 256) s[i] = src[i];
    __syncthreads();
    for (int idx = t; idx < 4096; idx += 256) {
        int a = idx >> 6, b = idx & 63;
        int na = (64 - a) & 63, nb = (64 - b) & 63;
        float v = s[a*64 + b]   + s[nb*64 + a]  + s[na*64 + nb] + s[b*64 + na]
                + s[b*64 + a]   + s[a*64 + nb]  + s[nb*64 + na] + s[na*64 + b];
        g_ksym[ch*4096 + idx] = v * 0.125f;
    }
}

// ---------------- forward DFT to the 63x32 grid ----------------
__global__ void __launch_bounds__(256) k_fft64(const float* __restrict__ f) {
    __shared__ float  ss[4096];
    __shared__ float2 sA[2048];
    int ch = blockIdx.x;
    const float* src = (ch < 128) ? (g_ksym + ch*4096) : (f + (ch-128)*4096);
    int t = threadIdx.x;
    for (int i = t; i < 4096; i += 256) ss[i] = src[i];
    __syncthreads();
    int k2 = t & 31, grp = t >> 5;
    {
        float2 acc[8];
        #pragma unroll
        for (int r = 0; r < 8; r++) acc[r] = make_float2(0.f, 0.f);
        for (int y = 0; y < 64; y++) {
            float2 e = g_Ey[y*32 + k2];
            #pragma unroll
            for (int r = 0; r < 8; r++) {
                float sv = ss[(grp*8 + r)*64 + y];
                acc[r].x = fmaf(sv, e.x, acc[r].x);
                acc[r].y = fmaf(sv, e.y, acc[r].y);
            }
        }
        #pragma unroll
        for (int r = 0; r < 8; r++) sA[(grp*8 + r)*32 + k2] = acc[r];
    }
    __syncthreads();
    {
        float2 acc[8];
        #pragma unroll
        for (int r = 0; r < 8; r++) acc[r] = make_float2(0.f, 0.f);
        for (int x = 0; x < 64; x++) {
            #pragma unroll
            for (int r = 0; r < 8; r++) {
                int m = grp*8 + r;
                float2 e = g_Ex[m*64 + x];
                float2 a = sA[x*32 + k2];
                acc[r].x = fmaf(e.x, a.x, fmaf(-e.y, a.y, acc[r].x));
                acc[r].y = fmaf(e.x, a.y, fmaf( e.y, a.x, acc[r].y));
            }
        }
        float2* dstF = (ch < 128) ? (g_Kf + ch*NF) : (g_Ff + (ch-128)*NF);
        #pragma unroll
        for (int r = 0; r < 8; r++) {
            int m = grp*8 + r;
            if (m < 63) dstF[m*32 + k2] = acc[r];
        }
    }
}

// ---------------- channel contraction ----------------
__global__ void k_conv() {
    int idx = blockIdx.x * 256 + threadIdx.x;
    int mk = idx % NF;
    int bj = idx / NF;
    int b = bj >> 4, j = bj & 15;
    float2 acc = make_float2(0.f, 0.f);
    #pragma unroll
    for (int i = 0; i < 8; i++) {
        float2 Fv = g_Ff[(b*8 + i)*NF + mk];
        float2 Kv = g_Kf[(i*16 + j)*NF + mk];
        acc.x = fmaf(Fv.x, Kv.x, fmaf(-Fv.y, Kv.y, acc.x));
        acc.y = fmaf(Fv.x, Kv.y, fmaf( Fv.y, Kv.x, acc.y));
    }
    g_Cf[bj*NF + mk] = acc;
}

// ---------------- stage1: Q[k2][n1] = sum_k1 WxT * G, with +/-k1 folding ----
// grid = 640 ch * 2 k2-halves. Writes g_Q[ch][k2*128+n1].
__global__ void __launch_bounds__(256) k_stage1() {
    __shared__ float2 Gs[NF];        // 16128 B
    __shared__ float4 SDh[31*16];    // 7936 B : (Sr,Si,Dr,Di) for this k2-half
    __shared__ float2 Zh[16];
    int ch = blockIdx.x >> 1, half = blockIdx.x & 1;
    int t = threadIdx.x;
    const float2* src; const float* mul = nullptr;
    if (ch < 128)      { src = g_Ff + ch*NF; }
    else if (ch < 384) { src = g_Cf + (ch-128)*NF; mul = g_MU; }
    else               { src = g_Cf + (ch-384)*NF; mul = g_MV; }
    float2* Qd = g_Q + (size_t)ch*4096;

    if (mul) {
        for (int i = t; i < NF; i += 256) {
            float2 cv = src[i]; float m = mul[i];
            Gs[i] = make_float2(-m*cv.y, m*cv.x);
        }
    } else {
        for (int i = t; i < NF; i += 256) Gs[i] = src[i];
    }
    __syncthreads();
    // build S/D for k2 in [half*16, half*16+16)
    for (int e = t; e < 496; e += 256) {
        int k1 = (e >> 4) + 1, k2 = half*16 + (e & 15);
        float2 gp = Gs[(31 + k1)*32 + k2];
        float2 gm = Gs[(31 - k1)*32 + k2];
        SDh[e] = make_float4(gp.x + gm.x, gp.y + gm.y, gp.x - gm.x, gp.y - gm.y);
    }
    if (t < 16) Zh[t] = Gs[31*32 + half*16 + t];
    __syncthreads();

    // n1 = 64 column (sin == 0)
    if (t < 16) {
        float2 z = Zh[t];
        float pr = z.x, pi = z.y;
        #pragma unroll
        for (int k1 = 1; k1 < 32; k1++) {
            float4 sd = SDh[(k1-1)*16 + t];
            float sgn = (k1 & 1) ? -1.0f : 1.0f;
            pr = fmaf(sgn, sd.x, pr);
            pi = fmaf(sgn, sd.y, pi);
        }
        Qd[(half*16 + t)*128 + 64] = make_float2(pr, pi);
    }

    // main: n1 = t&63, 4 k2 per thread
    {
        int n1 = t & 63, kg = t >> 6;
        float P[4], R[4], T[4], U[4];
        #pragma unroll
        for (int u = 0; u < 4; u++) { P[u]=0.f; R[u]=0.f; T[u]=0.f; U[u]=0.f; }
        for (int k1 = 1; k1 < 32; k1++) {
            float2 w = g_WxT[(31 + k1)*128 + n1];
            #pragma unroll
            for (int u = 0; u < 4; u++) {
                float4 sd = SDh[(k1-1)*16 + kg*4 + u];
                P[u] = fmaf(w.x, sd.x, P[u]);
                T[u] = fmaf(w.x, sd.y, T[u]);
                U[u] = fmaf(w.y, sd.z, U[u]);
                R[u] = fmaf(w.y, sd.w, R[u]);
            }
        }
        int n1p = (128 - n1) & 127;
        #pragma unroll
        for (int u = 0; u < 4; u++) {
            int k2 = half*16 + kg*4 + u;
            float2 z = Zh[kg*4 + u];
            Qd[k2*128 + n1]  = make_float2(z.x + P[u] - R[u], z.y + T[u] + U[u]);
            Qd[k2*128 + n1p] = make_float2(z.x + P[u] + R[u], z.y + T[u] - U[u]);
        }
    }
}

// ---------------- stage2: out(n1,n2) from Q, with n2 mirror folding ----------
// grid = 640 ch * 4 n1-tiles (32 rows each), 256 threads.
__global__ void __launch_bounds__(256) k_stage2(float* __restrict__ out) {
    __shared__ float2 Qt[32*32];     // [k2][n1loc] 8 KB
    int ch = blockIdx.x >> 2, n1base = (blockIdx.x & 3) * 32;
    int t = threadIdx.x;
    float* dst;
    if (ch < 128)      { int b = ch >> 3, c = ch & 7; dst = out + (size_t)(b*128 + c)*NPIX; }
    else if (ch < 384) { dst = g_u + (size_t)(ch-128)*NPIX; }
    else               { dst = g_v + (size_t)(ch-384)*NPIX; }
    const float2* Qsrc = g_Q + (size_t)ch*4096;
    for (int i = t; i < 1024; i += 256)
        Qt[i] = Qsrc[(i >> 5)*128 + n1base + (i & 31)];
    __syncthreads();

    // n2 = 64 column
    if (t < 32) {
        float acc = 0.f;
        #pragma unroll
        for (int k2 = 0; k2 < 32; k2++)
            acc = fmaf(g_WyT[k2*128 + 64].x, Qt[k2*32 + t].x, acc);
        dst[(n1base + t)*128 + 64] = acc;
    }

    // main: tx = n2 group (4 cols in 0..63), ty = n1 pair
    int tx = t & 15, ty = t >> 4;
    float E[2][4], O[2][4];
    #pragma unroll
    for (int r = 0; r < 2; r++)
        #pragma unroll
        for (int j = 0; j < 4; j++) { E[r][j] = 0.f; O[r][j] = 0.f; }
    for (int k2 = 0; k2 < 32; k2++) {
        float4 wa = *(const float4*)&g_WyT[k2*128 + tx*4];
        float4 wb = *(const float4*)&g_WyT[k2*128 + tx*4 + 2];
        float2 q0 = Qt[k2*32 + ty*2];
        float2 q1 = Qt[k2*32 + ty*2 + 1];
        E[0][0] = fmaf(q0.x, wa.x, E[0][0]);  O[0][0] = fmaf(q0.y, wa.y, O[0][0]);
        E[0][1] = fmaf(q0.x, wa.z, E[0][1]);  O[0][1] = fmaf(q0.y, wa.w, O[0][1]);
        E[0][2] = fmaf(q0.x, wb.x, E[0][2]);  O[0][2] = fmaf(q0.y, wb.y, O[0][2]);
        E[0][3] = fmaf(q0.x, wb.z, E[0][3]);  O[0][3] = fmaf(q0.y, wb.w, O[0][3]);
        E[1][0] = fmaf(q1.x, wa.x, E[1][0]);  O[1][0] = fmaf(q1.y, wa.y, O[1][0]);
        E[1][1] = fmaf(q1.x, wa.z, E[1][1]);  O[1][1] = fmaf(q1.y, wa.w, O[1][1]);
        E[1][2] = fmaf(q1.x, wb.x, E[1][2]);  O[1][2] = fmaf(q1.y, wb.y, O[1][2]);
        E[1][3] = fmaf(q1.x, wb.z, E[1][3]);  O[1][3] = fmaf(q1.y, wb.w, O[1][3]);
    }
    #pragma unroll
    for (int r = 0; r < 2; r++) {
        float* row = dst + (n1base + ty*2 + r)*128;
        *(float4*)(row + tx*4) = make_float4(E[r][0]-O[r][0], E[r][1]-O[r][1],
                                             E[r][2]-O[r][2], E[r][3]-O[r][3]);
        if (tx == 0) {
            row[127] = E[r][1] + O[r][1];
            row[126] = E[r][2] + O[r][2];
            row[125] = E[r][3] + O[r][3];
        } else {
            #pragma unroll
            for (int j = 0; j < 4; j++)
                row[128 - tx*4 - j] = E[r][j] + O[r][j];
        }
    }
}

// ---------------- cross products (vectorized stores) ----------------
// grid = 16 b * 128 n1, 128 threads: t&31 = n2-quad, t>>5 = pair-chunk (30 pairs)
__global__ void __launch_bounds__(128) k_cross(float* __restrict__ out) {
    __shared__ float us[16*128], vs[16*128];
    int b = blockIdx.x >> 7, n1 = blockIdx.x & 127;
    int t = threadIdx.x;
    for (int i = t; i < 16*128; i += 128) {
        int c = i >> 7, n2 = i & 127;
        us[i] = g_u[((size_t)(b*16 + c)*128 + n1)*128 + n2];
        vs[i] = g_v[((size_t)(b*16 + c)*128 + n1)*128 + n2];
    }
    __syncthreads();
    int q = t & 31, g = t >> 5;
    float* obase = out + ((size_t)b*128 + 8)*NPIX + n1*128 + q*4;
    #pragma unroll 2
    for (int pp = 0; pp < 30; pp++) {
        int p = g*30 + pp;
        int i = g_I[p], j = g_J[p];
        float4 ui = *(float4*)&us[i*128 + q*4];
        float4 vj = *(float4*)&vs[j*128 + q*4];
        float4 uj = *(float4*)&us[j*128 + q*4];
        float4 vi = *(float4*)&vs[i*128 + q*4];
        float4 r;
        r.x = ui.x*vj.x - uj.x*vi.x;
        r.y = ui.y*vj.y - uj.y*vi.y;
        r.z = ui.z*vj.z - uj.z*vi.z;
        r.w = ui.w*vj.w - uj.w*vi.w;
        *(float4*)(obase + (size_t)p*NPIX) = r;
    }
}

// ---------------- launch ----------------
extern "C" void kernel_launch(void* const* d_in, const int* in_sizes, int n_in,
                              void* d_out, int out_size) {
    const float* f    = (const float*)d_in[0];   // [16,8,64,64]
    const float* kern = (const float*)d_in[1];   // [1,8,16,64,64]
    float* out = (float*)d_out;                  // [16,128,128,128]
    (void)in_sizes; (void)n_in; (void)out_size;

    k_init   <<<40,   256>>>();
    k_sym    <<<128,  256>>>(kern);
    k_fft64  <<<256,  256>>>(f);
    k_conv   <<<2016, 256>>>();
    k_stage1 <<<1280, 256>>>();
    k_stage2 <<<2560, 256>>>(out);
    k_cross  <<<2048, 128>>>(out);
}

// round 4
// speedup vs baseline: 1.0542x; 1.0542x over previous
#include <cuda_runtime.h>
#include <math.h>

// Problem constants
#define NBATCH 16
#define NC1 8
#define NC2 16
#define NM 63
#define NK2 32
#define NF (NM*NK2)  /* 2016 */
#define NPIX 16384   /* 128*128 */

// ---------------- device scratch ----------------
__device__ float2  g_Kf[128*NF];
__device__ float2  g_Ff[128*NF];
__device__ float2  g_Cf[256*NF];
__device__ float   g_u[256*NPIX];
__device__ float   g_v[256*NPIX];
__device__ float2  g_Ey[64*32];
__device__ float2  g_Ex[64*64];
__device__ float2  g_WxT[63*128];
__device__ float2  g_WyT[32*128];
__device__ float   g_MU[NF];
__device__ float   g_MV[NF];
__device__ int     g_I[120], g_J[120];

// ---------------- table init (parallel) ----------------
__global__ void k_init() {
    int tid = blockIdx.x*256 + threadIdx.x;
    int stride = gridDim.x*256;
    for (int idx = tid; idx < 64*32; idx += stride) {
        int y = idx >> 5, k2 = idx & 31;
        float s, c; sincospif(-2.0f * (float)(k2*y) / 64.0f, &s, &c);
        g_Ey[idx] = make_float2(c, s);
    }
    for (int idx = tid; idx < 64*64; idx += stride) {
        int m = idx >> 6, x = idx & 63; int k1 = m - 31;
        float s, c; sincospif(-2.0f * (float)(k1*x) / 64.0f, &s, &c);
        g_Ex[idx] = make_float2(c, s);
    }
    for (int idx = tid; idx < 63*128; idx += stride) {
        int m = idx >> 7, n1 = idx & 127; int k1 = m - 31;
        float s, c; sincospif(2.0f * (float)(k1*n1) / 128.0f, &s, &c);
        g_WxT[idx] = make_float2(c, s);
    }
    for (int idx = tid; idx < 32*128; idx += stride) {
        int k2 = idx >> 7, n2 = idx & 127;
        float s, c; sincospif(2.0f * (float)(k2*n2) / 128.0f, &s, &c);
        float sc = ((k2 == 0) ? 1.0f : 2.0f) * (2.0f / 16384.0f);
        g_WyT[idx] = make_float2(c * sc, s * sc);
    }
    for (int idx = tid; idx < NF; idx += stride) {
        int m = idx >> 5, k2 = idx & 31; int k1 = m - 31;
        float den = (float)(k1*k1 + k2*k2);
        if (den == 0.0f) den = 1.0f;
        g_MU[idx] =  (float)k2 / den;
        g_MV[idx] = -(float)k1 / den;
    }
    for (int p = tid; p < 120; p += stride) {
        int off = p, i = 0, cnt = 15;
        while (off >= cnt) { off -= cnt; i++; cnt--; }
        g_I[p] = i; g_J[p] = i + 1 + off;
    }
}

// ---------------- forward DFT (with fused D4 symmetrization for kernel) ----
__global__ void __launch_bounds__(256) k_fft64(const float* __restrict__ f,
                                               const float* __restrict__ kin) {
    __shared__ float  ss[4096];      // [x][y]
    __shared__ float2 sA[2048];      // [x][k2]
    int ch = blockIdx.x;
    int t = threadIdx.x;
    bool isK = (ch < 128);
    const float* src = isK ? (kin + ch*4096) : (f + (ch-128)*4096);
    for (int i = t; i < 4096; i += 256) ss[i] = src[i];
    __syncthreads();
    if (isK) {
        // symmetrize in registers, then write back
        float rv[16];
        #pragma unroll
        for (int r = 0; r < 16; r++) {
            int idx = t + 256*r;
            int a = idx >> 6, b = idx & 63;
            int na = (64 - a) & 63, nb = (64 - b) & 63;
            rv[r] = (ss[a*64 + b]  + ss[nb*64 + a] + ss[na*64 + nb] + ss[b*64 + na]
                   + ss[b*64 + a]  + ss[a*64 + nb] + ss[nb*64 + na] + ss[na*64 + b]) * 0.125f;
        }
        __syncthreads();
        #pragma unroll
        for (int r = 0; r < 16; r++) ss[t + 256*r] = rv[r];
        __syncthreads();
    }
    int k2 = t & 31, grp = t >> 5;
    {
        float2 acc[8];
        #pragma unroll
        for (int r = 0; r < 8; r++) acc[r] = make_float2(0.f, 0.f);
        for (int y = 0; y < 64; y++) {
            float2 e = g_Ey[y*32 + k2];
            #pragma unroll
            for (int r = 0; r < 8; r++) {
                float sv = ss[(grp*8 + r)*64 + y];
                acc[r].x = fmaf(sv, e.x, acc[r].x);
                acc[r].y = fmaf(sv, e.y, acc[r].y);
            }
        }
        #pragma unroll
        for (int r = 0; r < 8; r++) sA[(grp*8 + r)*32 + k2] = acc[r];
    }
    __syncthreads();
    {
        float2 acc[8];
        #pragma unroll
        for (int r = 0; r < 8; r++) acc[r] = make_float2(0.f, 0.f);
        for (int x = 0; x < 64; x++) {
            #pragma unroll
            for (int r = 0; r < 8; r++) {
                int m = grp*8 + r;
                float2 e = g_Ex[m*64 + x];
                float2 a = sA[x*32 + k2];
                acc[r].x = fmaf(e.x, a.x, fmaf(-e.y, a.y, acc[r].x));
                acc[r].y = fmaf(e.x, a.y, fmaf( e.y, a.x, acc[r].y));
            }
        }
        float2* dstF = isK ? (g_Kf + ch*NF) : (g_Ff + (ch-128)*NF);
        #pragma unroll
        for (int r = 0; r < 8; r++) {
            int m = grp*8 + r;
            if (m < 63) dstF[m*32 + k2] = acc[r];
        }
    }
}

// ---------------- channel contraction ----------------
__global__ void k_conv() {
    int idx = blockIdx.x * 256 + threadIdx.x;
    int mk = idx % NF;
    int bj = idx / NF;
    int b = bj >> 4, j = bj & 15;
    float2 acc = make_float2(0.f, 0.f);
    #pragma unroll
    for (int i = 0; i < 8; i++) {
        float2 Fv = g_Ff[(b*8 + i)*NF + mk];
        float2 Kv = g_Kf[(i*16 + j)*NF + mk];
        acc.x = fmaf(Fv.x, Kv.x, fmaf(-Fv.y, Kv.y, acc.x));
        acc.y = fmaf(Fv.x, Kv.y, fmaf( Fv.y, Kv.x, acc.y));
    }
    g_Cf[bj*NF + mk] = acc;
}

// ---------------- fused inverse transform (persistent: 2 channels/block) ----
#define SM_Z    16384
#define SM_Q    16640
#define SM_TOT  (16640 + 32768)

__global__ void __launch_bounds__(256) k_itrans(float* __restrict__ out) {
    extern __shared__ char sm[];
    float2* Gs = (float2*)sm;                 // 2016 float2 (reused as SD)
    float4* SD = (float4*)sm;                 // SD[(k1-1)*32+k2]
    float2* Zs = (float2*)(sm + SM_Z);        // 32
    float2* Qs = (float2*)(sm + SM_Q);        // [k2][n1] 32x128

    int t = threadIdx.x;

    #pragma unroll 1
    for (int ci = 0; ci < 2; ci++) {
        int ch = blockIdx.x*2 + ci;
        const float2* src; float* dst; const float* mul = nullptr;
        if (ch < 128) {
            src = g_Ff + ch*NF;
            int b = ch >> 3, c = ch & 7;
            dst = out + (size_t)(b*128 + c) * NPIX;
        } else if (ch < 384) {
            int c2 = ch - 128; src = g_Cf + c2*NF; dst = g_u + (size_t)c2*NPIX; mul = g_MU;
        } else {
            int c2 = ch - 384; src = g_Cf + c2*NF; dst = g_v + (size_t)c2*NPIX; mul = g_MV;
        }

        // phase 0: load G (multiplier folded for u/v)
        if (mul) {
            for (int i = t; i < NF; i += 256) {
                float2 cv = src[i]; float m = mul[i];
                Gs[i] = make_float2(-m*cv.y, m*cv.x);
            }
        } else {
            for (int i = t; i < NF; i += 256) Gs[i] = src[i];
        }
        __syncthreads();

        // phase 1: build S/D pairs
        float4 rv[4];
        #pragma unroll
        for (int r = 0; r < 4; r++) {
            int e = t + 256*r;
            if (e < 992) {
                int k1 = (e >> 5) + 1, k2 = e & 31;
                float2 gp = Gs[(31 + k1)*32 + k2];
                float2 gm = Gs[(31 - k1)*32 + k2];
                rv[r] = make_float4(gp.x + gm.x, gp.y + gm.y, gp.x - gm.x, gp.y - gm.y);
            }
        }
        float2 zv;
        if (t < 32) zv = Gs[31*32 + t];
        __syncthreads();
        #pragma unroll
        for (int r = 0; r < 4; r++) {
            int e = t + 256*r;
            if (e < 992) SD[e] = rv[r];
        }
        if (t < 32) Zs[t] = zv;
        __syncthreads();

        // phase 2a: n1 = 64 column
        if (t < 32) {
            float2 z = Zs[t];
            float pr = z.x, pi = z.y;
            #pragma unroll
            for (int k1 = 1; k1 < 32; k1++) {
                float4 sd = SD[(k1-1)*32 + t];
                float sgn = (k1 & 1) ? -1.0f : 1.0f;
                pr = fmaf(sgn, sd.x, pr);
                pi = fmaf(sgn, sd.y, pi);
            }
            Qs[t*128 + 64] = make_float2(pr, pi);
        }

        // phase 2b: stage1 main — each thread: one n1h (0..63) x 8 k2
        {
            int n1 = t & 63, kg = t >> 6, k2b = kg*8;
            float P[8], R[8], T[8], U[8];
            #pragma unroll
            for (int u = 0; u < 8; u++) { P[u]=0.f; R[u]=0.f; T[u]=0.f; U[u]=0.f; }
            for (int k1 = 1; k1 < 32; k1++) {
                float2 w = g_WxT[(31 + k1)*128 + n1];
                #pragma unroll
                for (int u = 0; u < 8; u++) {
                    float4 sd = SD[(k1-1)*32 + k2b + u];
                    P[u] = fmaf(w.x, sd.x, P[u]);
                    T[u] = fmaf(w.x, sd.y, T[u]);
                    U[u] = fmaf(w.y, sd.z, U[u]);
                    R[u] = fmaf(w.y, sd.w, R[u]);
                }
            }
            int n1p = (128 - n1) & 127;
            #pragma unroll
            for (int u = 0; u < 8; u++) {
                float2 z = Zs[k2b + u];
                Qs[(k2b + u)*128 + n1]  = make_float2(z.x + P[u] - R[u], z.y + T[u] + U[u]);
                Qs[(k2b + u)*128 + n1p] = make_float2(z.x + P[u] + R[u], z.y + T[u] - U[u]);
            }
        }
        __syncthreads();

        // phase 3a: n2 = 64 column
        if (t < 128) {
            float acc = 0.f;
            for (int k2 = 0; k2 < 32; k2++)
                acc = fmaf(g_WyT[k2*128 + 64].x, Qs[k2*128 + t].x, acc);
            dst[t*128 + 64] = acc;
        }

        // phase 3b: stage2 main — 8 n1 x 4 n2h per thread
        {
            int tx = t & 15, ty = t >> 4;
            float E[8][4], O[8][4];
            #pragma unroll
            for (int u = 0; u < 8; u++)
                #pragma unroll
                for (int j = 0; j < 4; j++) { E[u][j] = 0.f; O[u][j] = 0.f; }
            for (int k2 = 0; k2 < 32; k2++) {
                float2 w[4];
                #pragma unroll
                for (int j = 0; j < 4; j++) w[j] = g_WyT[k2*128 + tx*4 + j];
                float qr[8], qi[8];
                #pragma unroll
                for (int u = 0; u < 8; u++) {
                    float2 q = Qs[k2*128 + ty*8 + u];
                    qr[u] = q.x; qi[u] = q.y;
                }
                #pragma unroll
                for (int u = 0; u < 8; u++)
                    #pragma unroll
                    for (int j = 0; j < 4; j++) {
                        E[u][j] = fmaf(qr[u], w[j].x, E[u][j]);
                        O[u][j] = fmaf(qi[u], w[j].y, O[u][j]);
                    }
            }
            #pragma unroll
            for (int u = 0; u < 8; u++) {
                float* row = dst + (ty*8 + u)*128;
                *(float4*)(row + tx*4) = make_float4(E[u][0]-O[u][0], E[u][1]-O[u][1],
                                                     E[u][2]-O[u][2], E[u][3]-O[u][3]);
                #pragma unroll
                for (int j = 0; j < 4; j++)
                    row[(128 - (tx*4 + j)) & 127] = E[u][j] + O[u][j];
            }
        }
        __syncthreads();   // protect smem reuse across channel iterations
    }
}

// ---------------- cross products (vectorized stores) ----------------
__global__ void __launch_bounds__(128) k_cross(float* __restrict__ out) {
    __shared__ float us[16*128], vs[16*128];
    int b = blockIdx.x >> 7, n1 = blockIdx.x & 127;
    int t = threadIdx.x;
    for (int i = t; i < 16*128; i += 128) {
        int c = i >> 7, n2 = i & 127;
        us[i] = g_u[((size_t)(b*16 + c)*128 + n1)*128 + n2];
        vs[i] = g_v[((size_t)(b*16 + c)*128 + n1)*128 + n2];
    }
    __syncthreads();
    int q = t & 31, g = t >> 5;
    float* obase = out + ((size_t)b*128 + 8)*NPIX + n1*128 + q*4;
    #pragma unroll 2
    for (int pp = 0; pp < 30; pp++) {
        int p = g*30 + pp;
        int i = g_I[p], j = g_J[p];
        float4 ui = *(float4*)&us[i*128 + q*4];
        float4 vj = *(float4*)&vs[j*128 + q*4];
        float4 uj = *(float4*)&us[j*128 + q*4];
        float4 vi = *(float4*)&vs[i*128 + q*4];
        float4 r;
        r.x = ui.x*vj.x - uj.x*vi.x;
        r.y = ui.y*vj.y - uj.y*vi.y;
        r.z = ui.z*vj.z - uj.z*vi.z;
        r.w = ui.w*vj.w - uj.w*vi.w;
        *(float4*)(obase + (size_t)p*NPIX) = r;
    }
}

// ---------------- launch ----------------
extern "C" void kernel_launch(void* const* d_in, const int* in_sizes, int n_in,
                              void* d_out, int out_size) {
    const float* f    = (const float*)d_in[0];   // [16,8,64,64]
    const float* kern = (const float*)d_in[1];   // [1,8,16,64,64]
    float* out = (float*)d_out;                  // [16,128,128,128]
    (void)in_sizes; (void)n_in; (void)out_size;

    cudaFuncSetAttribute(k_itrans, cudaFuncAttributeMaxDynamicSharedMemorySize, SM_TOT);

    k_init   <<<40,   256>>>();
    k_fft64  <<<256,  256>>>(f, kern);
    k_conv   <<<2016, 256>>>();
    k_itrans <<<320,  256, SM_TOT>>>(out);
    k_cross  <<<2048, 128>>>(out);
}

// round 5
// speedup vs baseline: 1.1179x; 1.0604x over previous
#include <cuda_runtime.h>
#include <math.h>

// Problem constants
#define NBATCH 16
#define NC1 8
#define NC2 16
#define NM 63
#define NK2 32
#define NF (NM*NK2)  /* 2016 */
#define NPIX 16384   /* 128*128 */

// ---------------- device scratch ----------------
__device__ float2  g_Kf[128*NF];
__device__ float2  g_Ff[128*NF];
__device__ float2  g_Cf[256*NF];
__device__ float   g_u[256*NPIX];
__device__ float   g_v[256*NPIX];
__device__ float2  g_Ey[64*32];
__device__ float2  g_Ex[64*64];
__device__ float2  g_WxT[63*128];
__device__ float2  g_WyT[32*128];
__device__ float   g_MU[NF];
__device__ float   g_MV[NF];
__device__ int     g_I[120], g_J[120];

// ---------------- table init (parallel) ----------------
__global__ void k_init() {
    int tid = blockIdx.x*256 + threadIdx.x;
    int stride = gridDim.x*256;
    for (int idx = tid; idx < 64*32; idx += stride) {
        int y = idx >> 5, k2 = idx & 31;
        float s, c; sincospif(-2.0f * (float)(k2*y) / 64.0f, &s, &c);
        g_Ey[idx] = make_float2(c, s);
    }
    for (int idx = tid; idx < 64*64; idx += stride) {
        int m = idx >> 6, x = idx & 63; int k1 = m - 31;
        float s, c; sincospif(-2.0f * (float)(k1*x) / 64.0f, &s, &c);
        g_Ex[idx] = make_float2(c, s);
    }
    for (int idx = tid; idx < 63*128; idx += stride) {
        int m = idx >> 7, n1 = idx & 127; int k1 = m - 31;
        float s, c; sincospif(2.0f * (float)(k1*n1) / 128.0f, &s, &c);
        g_WxT[idx] = make_float2(c, s);
    }
    for (int idx = tid; idx < 32*128; idx += stride) {
        int k2 = idx >> 7, n2 = idx & 127;
        float s, c; sincospif(2.0f * (float)(k2*n2) / 128.0f, &s, &c);
        float sc = ((k2 == 0) ? 1.0f : 2.0f) * (2.0f / 16384.0f);
        g_WyT[idx] = make_float2(c * sc, s * sc);
    }
    for (int idx = tid; idx < NF; idx += stride) {
        int m = idx >> 5, k2 = idx & 31; int k1 = m - 31;
        float den = (float)(k1*k1 + k2*k2);
        if (den == 0.0f) den = 1.0f;
        g_MU[idx] =  (float)k2 / den;
        g_MV[idx] = -(float)k1 / den;
    }
    for (int p = tid; p < 120; p += stride) {
        int off = p, i = 0, cnt = 15;
        while (off >= cnt) { off -= cnt; i++; cnt--; }
        g_I[p] = i; g_J[p] = i + 1 + off;
    }
}

// ---------------- forward DFT (512 threads; fused D4 symmetrization) ----
__global__ void __launch_bounds__(512) k_fft64(const float* __restrict__ f,
                                               const float* __restrict__ kin) {
    __shared__ float  ss[4096];      // [x][y]
    __shared__ float2 sA[2048];      // [x][k2]
    int ch = blockIdx.x;
    int t = threadIdx.x;
    bool isK = (ch < 128);
    const float* src = isK ? (kin + ch*4096) : (f + (ch-128)*4096);
    for (int i = t; i < 4096; i += 512) ss[i] = src[i];
    __syncthreads();
    if (isK) {
        float rv[8];
        #pragma unroll
        for (int r = 0; r < 8; r++) {
            int idx = t + 512*r;
            int a = idx >> 6, b = idx & 63;
            int na = (64 - a) & 63, nb = (64 - b) & 63;
            rv[r] = (ss[a*64 + b]  + ss[nb*64 + a] + ss[na*64 + nb] + ss[b*64 + na]
                   + ss[b*64 + a]  + ss[a*64 + nb] + ss[nb*64 + na] + ss[na*64 + b]) * 0.125f;
        }
        __syncthreads();
        #pragma unroll
        for (int r = 0; r < 8; r++) ss[t + 512*r] = rv[r];
        __syncthreads();
    }
    int k2 = t & 31, grp = t >> 5;   // grp in 0..15, 4 rows each
    {
        float2 acc[4];
        #pragma unroll
        for (int r = 0; r < 4; r++) acc[r] = make_float2(0.f, 0.f);
        for (int y = 0; y < 64; y++) {
            float2 e = g_Ey[y*32 + k2];
            #pragma unroll
            for (int r = 0; r < 4; r++) {
                float sv = ss[(grp*4 + r)*64 + y];
                acc[r].x = fmaf(sv, e.x, acc[r].x);
                acc[r].y = fmaf(sv, e.y, acc[r].y);
            }
        }
        #pragma unroll
        for (int r = 0; r < 4; r++) sA[(grp*4 + r)*32 + k2] = acc[r];
    }
    __syncthreads();
    {
        float2 acc[4];
        #pragma unroll
        for (int r = 0; r < 4; r++) acc[r] = make_float2(0.f, 0.f);
        for (int x = 0; x < 64; x++) {
            #pragma unroll
            for (int r = 0; r < 4; r++) {
                int m = grp*4 + r;
                float2 e = g_Ex[m*64 + x];
                float2 a = sA[x*32 + k2];
                acc[r].x = fmaf(e.x, a.x, fmaf(-e.y, a.y, acc[r].x));
                acc[r].y = fmaf(e.x, a.y, fmaf( e.y, a.x, acc[r].y));
            }
        }
        float2* dstF = isK ? (g_Kf + ch*NF) : (g_Ff + (ch-128)*NF);
        #pragma unroll
        for (int r = 0; r < 4; r++) {
            int m = grp*4 + r;
            if (m < 63) dstF[m*32 + k2] = acc[r];
        }
    }
}

// ---------------- channel contraction ----------------
__global__ void k_conv() {
    int idx = blockIdx.x * 256 + threadIdx.x;
    int mk = idx % NF;
    int bj = idx / NF;
    int b = bj >> 4, j = bj & 15;
    float2 acc = make_float2(0.f, 0.f);
    #pragma unroll
    for (int i = 0; i < 8; i++) {
        float2 Fv = g_Ff[(b*8 + i)*NF + mk];
        float2 Kv = g_Kf[(i*16 + j)*NF + mk];
        acc.x = fmaf(Fv.x, Kv.x, fmaf(-Fv.y, Kv.y, acc.x));
        acc.y = fmaf(Fv.x, Kv.y, fmaf( Fv.y, Kv.x, acc.y));
    }
    g_Cf[bj*NF + mk] = acc;
}

// ---------------- fused inverse transform (64-reg, 4 CTA/SM) ----------------
#define SM_Z    16384
#define SM_Q    16640
#define SM_TOT  (16640 + 32768)

__global__ void __launch_bounds__(256, 4) k_itrans(float* __restrict__ out) {
    extern __shared__ char sm[];
    float2* Gs = (float2*)sm;                 // 2016 float2 (reused as SD)
    float4* SD = (float4*)sm;                 // SD[(k1-1)*32+k2]
    float2* Zs = (float2*)(sm + SM_Z);        // 32
    float2* Qs = (float2*)(sm + SM_Q);        // [k2][n1] 32x128

    int t = threadIdx.x;
    int ch = blockIdx.x;
    const float2* src; float* dst; const float* mul = nullptr;
    if (ch < 128) {
        src = g_Ff + ch*NF;
        int b = ch >> 3, c = ch & 7;
        dst = out + (size_t)(b*128 + c) * NPIX;
    } else if (ch < 384) {
        int c2 = ch - 128; src = g_Cf + c2*NF; dst = g_u + (size_t)c2*NPIX; mul = g_MU;
    } else {
        int c2 = ch - 384; src = g_Cf + c2*NF; dst = g_v + (size_t)c2*NPIX; mul = g_MV;
    }

    // phase 0: load G (multiplier folded for u/v)
    if (mul) {
        for (int i = t; i < NF; i += 256) {
            float2 cv = src[i]; float m = mul[i];
            Gs[i] = make_float2(-m*cv.y, m*cv.x);
        }
    } else {
        for (int i = t; i < NF; i += 256) Gs[i] = src[i];
    }
    __syncthreads();

    // phase 1: build S/D pairs
    float4 rv[4];
    #pragma unroll
    for (int r = 0; r < 4; r++) {
        int e = t + 256*r;
        if (e < 992) {
            int k1 = (e >> 5) + 1, k2 = e & 31;
            float2 gp = Gs[(31 + k1)*32 + k2];
            float2 gm = Gs[(31 - k1)*32 + k2];
            rv[r] = make_float4(gp.x + gm.x, gp.y + gm.y, gp.x - gm.x, gp.y - gm.y);
        }
    }
    float2 zv;
    if (t < 32) zv = Gs[31*32 + t];
    __syncthreads();
    #pragma unroll
    for (int r = 0; r < 4; r++) {
        int e = t + 256*r;
        if (e < 992) SD[e] = rv[r];
    }
    if (t < 32) Zs[t] = zv;
    __syncthreads();

    // phase 2a: n1 = 64 column
    if (t < 32) {
        float2 z = Zs[t];
        float pr = z.x, pi = z.y;
        #pragma unroll
        for (int k1 = 1; k1 < 32; k1++) {
            float4 sd = SD[(k1-1)*32 + t];
            float sgn = (k1 & 1) ? -1.0f : 1.0f;
            pr = fmaf(sgn, sd.x, pr);
            pi = fmaf(sgn, sd.y, pi);
        }
        Qs[t*128 + 64] = make_float2(pr, pi);
    }

    // phase 2b: stage1 main — each thread: one n1h (0..63) x 8 k2
    {
        int n1 = t & 63, kg = t >> 6, k2b = kg*8;
        float P[8], R[8], T[8], U[8];
        #pragma unroll
        for (int u = 0; u < 8; u++) { P[u]=0.f; R[u]=0.f; T[u]=0.f; U[u]=0.f; }
        for (int k1 = 1; k1 < 32; k1++) {
            float2 w = g_WxT[(31 + k1)*128 + n1];
            #pragma unroll
            for (int u = 0; u < 8; u++) {
                float4 sd = SD[(k1-1)*32 + k2b + u];
                P[u] = fmaf(w.x, sd.x, P[u]);
                T[u] = fmaf(w.x, sd.y, T[u]);
                U[u] = fmaf(w.y, sd.z, U[u]);
                R[u] = fmaf(w.y, sd.w, R[u]);
            }
        }
        int n1p = (128 - n1) & 127;
        #pragma unroll
        for (int u = 0; u < 8; u++) {
            float2 z = Zs[k2b + u];
            Qs[(k2b + u)*128 + n1]  = make_float2(z.x + P[u] - R[u], z.y + T[u] + U[u]);
            Qs[(k2b + u)*128 + n1p] = make_float2(z.x + P[u] + R[u], z.y + T[u] - U[u]);
        }
    }
    __syncthreads();

    // phase 3a: n2 = 64 column
    if (t < 128) {
        float acc = 0.f;
        for (int k2 = 0; k2 < 32; k2++)
            acc = fmaf(g_WyT[k2*128 + 64].x, Qs[k2*128 + t].x, acc);
        dst[t*128 + 64] = acc;
    }

    // phase 3b: stage2 main — two passes of 4 n1-rows x 4 n2h (keeps regs < 64)
    {
        int tx = t & 15, ty = t >> 4;
        #pragma unroll 1
        for (int p = 0; p < 2; p++) {
            int ubase = ty*8 + p*4;
            float E[4][4], O[4][4];
            #pragma unroll
            for (int u = 0; u < 4; u++)
                #pragma unroll
                for (int j = 0; j < 4; j++) { E[u][j] = 0.f; O[u][j] = 0.f; }
            for (int k2 = 0; k2 < 32; k2++) {
                float4 wa = *(const float4*)&g_WyT[k2*128 + tx*4];
                float4 wb = *(const float4*)&g_WyT[k2*128 + tx*4 + 2];
                float qr[4], qi[4];
                #pragma unroll
                for (int u = 0; u < 4; u++) {
                    float2 q = Qs[k2*128 + ubase + u];
                    qr[u] = q.x; qi[u] = q.y;
                }
                #pragma unroll
                for (int u = 0; u < 4; u++) {
                    E[u][0] = fmaf(qr[u], wa.x, E[u][0]);  O[u][0] = fmaf(qi[u], wa.y, O[u][0]);
                    E[u][1] = fmaf(qr[u], wa.z, E[u][1]);  O[u][1] = fmaf(qi[u], wa.w, O[u][1]);
                    E[u][2] = fmaf(qr[u], wb.x, E[u][2]);  O[u][2] = fmaf(qi[u], wb.y, O[u][2]);
                    E[u][3] = fmaf(qr[u], wb.z, E[u][3]);  O[u][3] = fmaf(qi[u], wb.w, O[u][3]);
                }
            }
            #pragma unroll
            for (int u = 0; u < 4; u++) {
                float* row = dst + (ubase + u)*128;
                *(float4*)(row + tx*4) = make_float4(E[u][0]-O[u][0], E[u][1]-O[u][1],
                                                     E[u][2]-O[u][2], E[u][3]-O[u][3]);
                #pragma unroll
                for (int j = 0; j < 4; j++)
                    row[(128 - (tx*4 + j)) & 127] = E[u][j] + O[u][j];
            }
        }
    }
}

// ---------------- cross products (vectorized stores) ----------------
__global__ void __launch_bounds__(128) k_cross(float* __restrict__ out) {
    __shared__ float us[16*128], vs[16*128];
    int b = blockIdx.x >> 7, n1 = blockIdx.x & 127;
    int t = threadIdx.x;
    for (int i = t; i < 16*128; i += 128) {
        int c = i >> 7, n2 = i & 127;
        us[i] = g_u[((size_t)(b*16 + c)*128 + n1)*128 + n2];
        vs[i] = g_v[((size_t)(b*16 + c)*128 + n1)*128 + n2];
    }
    __syncthreads();
    int q = t & 31, g = t >> 5;
    float* obase = out + ((size_t)b*128 + 8)*NPIX + n1*128 + q*4;
    #pragma unroll 2
    for (int pp = 0; pp < 30; pp++) {
        int p = g*30 + pp;
        int i = g_I[p], j = g_J[p];
        float4 ui = *(float4*)&us[i*128 + q*4];
        float4 vj = *(float4*)&vs[j*128 + q*4];
        float4 uj = *(float4*)&us[j*128 + q*4];
        float4 vi = *(float4*)&vs[i*128 + q*4];
        float4 r;
        r.x = ui.x*vj.x - uj.x*vi.x;
        r.y = ui.y*vj.y - uj.y*vi.y;
        r.z = ui.z*vj.z - uj.z*vi.z;
        r.w = ui.w*vj.w - uj.w*vi.w;
        *(float4*)(obase + (size_t)p*NPIX) = r;
    }
}

// ---------------- launch ----------------
extern "C" void kernel_launch(void* const* d_in, const int* in_sizes, int n_in,
                              void* d_out, int out_size) {
    const float* f    = (const float*)d_in[0];   // [16,8,64,64]
    const float* kern = (const float*)d_in[1];   // [1,8,16,64,64]
    float* out = (float*)d_out;                  // [16,128,128,128]
    (void)in_sizes; (void)n_in; (void)out_size;

    cudaFuncSetAttribute(k_itrans, cudaFuncAttributeMaxDynamicSharedMemorySize, SM_TOT);

    k_init   <<<40,   256>>>();
    k_fft64  <<<256,  512>>>(f, kern);
    k_conv   <<<2016, 256>>>();
    k_itrans <<<640,  256, SM_TOT>>>(out);
    k_cross  <<<2048, 128>>>(out);
}

// round 6
// speedup vs baseline: 1.1867x; 1.0615x over previous
#include <cuda_runtime.h>
#include <math.h>

// Problem constants
#define NBATCH 16
#define NC1 8
#define NC2 16
#define NM 63
#define NK2 32
#define NF (NM*NK2)  /* 2016 */
#define NPIX 16384   /* 128*128 */

// ---------------- device scratch ----------------
__device__ float2  g_Kf[128*NF];
__device__ float2  g_Ff[128*NF];
__device__ float2  g_Cf[256*NF];
__device__ float   g_u[256*NPIX];
__device__ float   g_v[256*NPIX];
__device__ float2  g_Ey[64*32];
__device__ float2  g_Ex[64*64];
__device__ float2  g_WxT[63*128];
__device__ float2  g_WyT[32*128];
__device__ float   g_MU[NF];
__device__ float   g_MV[NF];
__device__ int     g_I[120], g_J[120];

// ---------------- table init (parallel) ----------------
__global__ void k_init() {
    int tid = blockIdx.x*256 + threadIdx.x;
    int stride = gridDim.x*256;
    for (int idx = tid; idx < 64*32; idx += stride) {
        int y = idx >> 5, k2 = idx & 31;
        float s, c; sincospif(-2.0f * (float)(k2*y) / 64.0f, &s, &c);
        g_Ey[idx] = make_float2(c, s);
    }
    for (int idx = tid; idx < 64*64; idx += stride) {
        int m = idx >> 6, x = idx & 63; int k1 = m - 31;
        float s, c; sincospif(-2.0f * (float)(k1*x) / 64.0f, &s, &c);
        g_Ex[idx] = make_float2(c, s);
    }
    for (int idx = tid; idx < 63*128; idx += stride) {
        int m = idx >> 7, n1 = idx & 127; int k1 = m - 31;
        float s, c; sincospif(2.0f * (float)(k1*n1) / 128.0f, &s, &c);
        g_WxT[idx] = make_float2(c, s);
    }
    for (int idx = tid; idx < 32*128; idx += stride) {
        int k2 = idx >> 7, n2 = idx & 127;
        float s, c; sincospif(2.0f * (float)(k2*n2) / 128.0f, &s, &c);
        float sc = ((k2 == 0) ? 1.0f : 2.0f) * (2.0f / 16384.0f);
        g_WyT[idx] = make_float2(c * sc, s * sc);
    }
    for (int idx = tid; idx < NF; idx += stride) {
        int m = idx >> 5, k2 = idx & 31; int k1 = m - 31;
        float den = (float)(k1*k1 + k2*k2);
        if (den == 0.0f) den = 1.0f;
        g_MU[idx] =  (float)k2 / den;
        g_MV[idx] = -(float)k1 / den;
    }
    for (int p = tid; p < 120; p += stride) {
        int off = p, i = 0, cnt = 15;
        while (off >= cnt) { off -= cnt; i++; cnt--; }
        g_I[p] = i; g_J[p] = i + 1 + off;
    }
}

// ---------------- forward DFT (512 threads; fused D4 symmetrization) ----
__global__ void __launch_bounds__(512) k_fft64(const float* __restrict__ f,
                                               const float* __restrict__ kin) {
    __shared__ float  ss[4096];      // [x][y]
    __shared__ float2 sA[2048];      // [x][k2]
    int ch = blockIdx.x;
    int t = threadIdx.x;
    bool isK = (ch < 128);
    const float* src = isK ? (kin + ch*4096) : (f + (ch-128)*4096);
    for (int i = t; i < 4096; i += 512) ss[i] = src[i];
    __syncthreads();
    if (isK) {
        float rv[8];
        #pragma unroll
        for (int r = 0; r < 8; r++) {
            int idx = t + 512*r;
            int a = idx >> 6, b = idx & 63;
            int na = (64 - a) & 63, nb = (64 - b) & 63;
            rv[r] = (ss[a*64 + b]  + ss[nb*64 + a] + ss[na*64 + nb] + ss[b*64 + na]
                   + ss[b*64 + a]  + ss[a*64 + nb] + ss[nb*64 + na] + ss[na*64 + b]) * 0.125f;
        }
        __syncthreads();
        #pragma unroll
        for (int r = 0; r < 8; r++) ss[t + 512*r] = rv[r];
        __syncthreads();
    }
    int k2 = t & 31, grp = t >> 5;
    {
        float2 acc[4];
        #pragma unroll
        for (int r = 0; r < 4; r++) acc[r] = make_float2(0.f, 0.f);
        for (int y = 0; y < 64; y++) {
            float2 e = g_Ey[y*32 + k2];
            #pragma unroll
            for (int r = 0; r < 4; r++) {
                float sv = ss[(grp*4 + r)*64 + y];
                acc[r].x = fmaf(sv, e.x, acc[r].x);
                acc[r].y = fmaf(sv, e.y, acc[r].y);
            }
        }
        #pragma unroll
        for (int r = 0; r < 4; r++) sA[(grp*4 + r)*32 + k2] = acc[r];
    }
    __syncthreads();
    {
        float2 acc[4];
        #pragma unroll
        for (int r = 0; r < 4; r++) acc[r] = make_float2(0.f, 0.f);
        for (int x = 0; x < 64; x++) {
            #pragma unroll
            for (int r = 0; r < 4; r++) {
                int m = grp*4 + r;
                float2 e = g_Ex[m*64 + x];
                float2 a = sA[x*32 + k2];
                acc[r].x = fmaf(e.x, a.x, fmaf(-e.y, a.y, acc[r].x));
                acc[r].y = fmaf(e.x, a.y, fmaf( e.y, a.x, acc[r].y));
            }
        }
        float2* dstF = isK ? (g_Kf + ch*NF) : (g_Ff + (ch-128)*NF);
        #pragma unroll
        for (int r = 0; r < 4; r++) {
            int m = grp*4 + r;
            if (m < 63) dstF[m*32 + k2] = acc[r];
        }
    }
}

// ---------------- channel contraction ----------------
__global__ void k_conv() {
    int idx = blockIdx.x * 256 + threadIdx.x;
    int mk = idx % NF;
    int bj = idx / NF;
    int b = bj >> 4, j = bj & 15;
    float2 acc = make_float2(0.f, 0.f);
    #pragma unroll
    for (int i = 0; i < 8; i++) {
        float2 Fv = g_Ff[(b*8 + i)*NF + mk];
        float2 Kv = g_Kf[(i*16 + j)*NF + mk];
        acc.x = fmaf(Fv.x, Kv.x, fmaf(-Fv.y, Kv.y, acc.x));
        acc.y = fmaf(Fv.x, Kv.y, fmaf( Fv.y, Kv.x, acc.y));
    }
    g_Cf[bj*NF + mk] = acc;
}

// ---------------- fused inverse transform (3 CTA/SM, ~85 regs for MLP) ------
#define SM_Z    16384
#define SM_Q    16640
#define SM_TOT  (16640 + 32768)

__global__ void __launch_bounds__(256, 3) k_itrans(float* __restrict__ out) {
    extern __shared__ char sm[];
    float2* Gs = (float2*)sm;                 // 2016 float2 (reused as SD)
    float4* SD = (float4*)sm;                 // SD[(k1-1)*32+k2]
    float2* Zs = (float2*)(sm + SM_Z);        // 32
    float2* Qs = (float2*)(sm + SM_Q);        // [k2][n1] 32x128

    int t = threadIdx.x;
    int ch = blockIdx.x;
    const float2* src; float* dst; const float* mul = nullptr;
    if (ch < 128) {
        src = g_Ff + ch*NF;
        int b = ch >> 3, c = ch & 7;
        dst = out + (size_t)(b*128 + c) * NPIX;
    } else if (ch < 384) {
        int c2 = ch - 128; src = g_Cf + c2*NF; dst = g_u + (size_t)c2*NPIX; mul = g_MU;
    } else {
        int c2 = ch - 384; src = g_Cf + c2*NF; dst = g_v + (size_t)c2*NPIX; mul = g_MV;
    }

    // phase 0: load G (multiplier folded for u/v)
    if (mul) {
        for (int i = t; i < NF; i += 256) {
            float2 cv = src[i]; float m = mul[i];
            Gs[i] = make_float2(-m*cv.y, m*cv.x);
        }
    } else {
        for (int i = t; i < NF; i += 256) Gs[i] = src[i];
    }
    __syncthreads();

    // phase 1: build S/D pairs
    float4 rv[4];
    #pragma unroll
    for (int r = 0; r < 4; r++) {
        int e = t + 256*r;
        if (e < 992) {
            int k1 = (e >> 5) + 1, k2 = e & 31;
            float2 gp = Gs[(31 + k1)*32 + k2];
            float2 gm = Gs[(31 - k1)*32 + k2];
            rv[r] = make_float4(gp.x + gm.x, gp.y + gm.y, gp.x - gm.x, gp.y - gm.y);
        }
    }
    float2 zv;
    if (t < 32) zv = Gs[31*32 + t];
    __syncthreads();
    #pragma unroll
    for (int r = 0; r < 4; r++) {
        int e = t + 256*r;
        if (e < 992) SD[e] = rv[r];
    }
    if (t < 32) Zs[t] = zv;
    __syncthreads();

    // phase 2a: n1 = 64 column
    if (t < 32) {
        float2 z = Zs[t];
        float pr = z.x, pi = z.y;
        #pragma unroll
        for (int k1 = 1; k1 < 32; k1++) {
            float4 sd = SD[(k1-1)*32 + t];
            float sgn = (k1 & 1) ? -1.0f : 1.0f;
            pr = fmaf(sgn, sd.x, pr);
            pi = fmaf(sgn, sd.y, pi);
        }
        Qs[t*128 + 64] = make_float2(pr, pi);
    }

    // phase 2b: stage1 main — one n1h x 8 k2; batch all 8 SD loads per k1
    {
        int n1 = t & 63, kg = t >> 6, k2b = kg*8;
        float P[8], R[8], T[8], U[8];
        #pragma unroll
        for (int u = 0; u < 8; u++) { P[u]=0.f; R[u]=0.f; T[u]=0.f; U[u]=0.f; }
        #pragma unroll 1
        for (int k1 = 1; k1 < 32; k1++) {
            float2 w = g_WxT[(31 + k1)*128 + n1];
            float4 sd[8];
            #pragma unroll
            for (int u = 0; u < 8; u++) sd[u] = SD[(k1-1)*32 + k2b + u];
            #pragma unroll
            for (int u = 0; u < 8; u++) {
                P[u] = fmaf(w.x, sd[u].x, P[u]);
                T[u] = fmaf(w.x, sd[u].y, T[u]);
                U[u] = fmaf(w.y, sd[u].z, U[u]);
                R[u] = fmaf(w.y, sd[u].w, R[u]);
            }
        }
        int n1p = (128 - n1) & 127;
        #pragma unroll
        for (int u = 0; u < 8; u++) {
            float2 z = Zs[k2b + u];
            Qs[(k2b + u)*128 + n1]  = make_float2(z.x + P[u] - R[u], z.y + T[u] + U[u]);
            Qs[(k2b + u)*128 + n1p] = make_float2(z.x + P[u] + R[u], z.y + T[u] - U[u]);
        }
    }
    __syncthreads();

    // phase 3a: n2 = 64 column
    if (t < 128) {
        float acc = 0.f;
        for (int k2 = 0; k2 < 32; k2++)
            acc = fmaf(g_WyT[k2*128 + 64].x, Qs[k2*128 + t].x, acc);
        dst[t*128 + 64] = acc;
    }

    // phase 3b: stage2 main — two passes of 4 n1-rows x 4 n2h, batched loads
    {
        int tx = t & 15, ty = t >> 4;
        #pragma unroll 1
        for (int p = 0; p < 2; p++) {
            int ubase = ty*8 + p*4;
            float E[4][4], O[4][4];
            #pragma unroll
            for (int u = 0; u < 4; u++)
                #pragma unroll
                for (int j = 0; j < 4; j++) { E[u][j] = 0.f; O[u][j] = 0.f; }
            #pragma unroll 2
            for (int k2 = 0; k2 < 32; k2++) {
                float4 wa = *(const float4*)&g_WyT[k2*128 + tx*4];
                float4 wb = *(const float4*)&g_WyT[k2*128 + tx*4 + 2];
                float2 q[4];
                #pragma unroll
                for (int u = 0; u < 4; u++) q[u] = Qs[k2*128 + ubase + u];
                #pragma unroll
                for (int u = 0; u < 4; u++) {
                    E[u][0] = fmaf(q[u].x, wa.x, E[u][0]);  O[u][0] = fmaf(q[u].y, wa.y, O[u][0]);
                    E[u][1] = fmaf(q[u].x, wa.z, E[u][1]);  O[u][1] = fmaf(q[u].y, wa.w, O[u][1]);
                    E[u][2] = fmaf(q[u].x, wb.x, E[u][2]);  O[u][2] = fmaf(q[u].y, wb.y, O[u][2]);
                    E[u][3] = fmaf(q[u].x, wb.z, E[u][3]);  O[u][3] = fmaf(q[u].y, wb.w, O[u][3]);
                }
            }
            #pragma unroll
            for (int u = 0; u < 4; u++) {
                float* row = dst + (ubase + u)*128;
                *(float4*)(row + tx*4) = make_float4(E[u][0]-O[u][0], E[u][1]-O[u][1],
                                                     E[u][2]-O[u][2], E[u][3]-O[u][3]);
                #pragma unroll
                for (int j = 0; j < 4; j++)
                    row[(128 - (tx*4 + j)) & 127] = E[u][j] + O[u][j];
            }
        }
    }
}

// ---------------- cross products (vectorized stores) ----------------
__global__ void __launch_bounds__(128) k_cross(float* __restrict__ out) {
    __shared__ float us[16*128], vs[16*128];
    int b = blockIdx.x >> 7, n1 = blockIdx.x & 127;
    int t = threadIdx.x;
    for (int i = t; i < 16*128; i += 128) {
        int c = i >> 7, n2 = i & 127;
        us[i] = g_u[((size_t)(b*16 + c)*128 + n1)*128 + n2];
        vs[i] = g_v[((size_t)(b*16 + c)*128 + n1)*128 + n2];
    }
    __syncthreads();
    int q = t & 31, g = t >> 5;
    float* obase = out + ((size_t)b*128 + 8)*NPIX + n1*128 + q*4;
    #pragma unroll 2
    for (int pp = 0; pp < 30; pp++) {
        int p = g*30 + pp;
        int i = g_I[p], j = g_J[p];
        float4 ui = *(float4*)&us[i*128 + q*4];
        float4 vj = *(float4*)&vs[j*128 + q*4];
        float4 uj = *(float4*)&us[j*128 + q*4];
        float4 vi = *(float4*)&vs[i*128 + q*4];
        float4 r;
        r.x = ui.x*vj.x - uj.x*vi.x;
        r.y = ui.y*vj.y - uj.y*vi.y;
        r.z = ui.z*vj.z - uj.z*vi.z;
        r.w = ui.w*vj.w - uj.w*vi.w;
        *(float4*)(obase + (size_t)p*NPIX) = r;
    }
}

// ---------------- launch ----------------
extern "C" void kernel_launch(void* const* d_in, const int* in_sizes, int n_in,
                              void* d_out, int out_size) {
    const float* f    = (const float*)d_in[0];   // [16,8,64,64]
    const float* kern = (const float*)d_in[1];   // [1,8,16,64,64]
    float* out = (float*)d_out;                  // [16,128,128,128]
    (void)in_sizes; (void)n_in; (void)out_size;

    cudaFuncSetAttribute(k_itrans, cudaFuncAttributeMaxDynamicSharedMemorySize, SM_TOT);

    k_init   <<<40,   256>>>();
    k_fft64  <<<256,  512>>>(f, kern);
    k_conv   <<<2016, 256>>>();
    k_itrans <<<640,  256, SM_TOT>>>(out);
    k_cross  <<<2048, 128>>>(out);
}